// round 16
// baseline (speedup 1.0000x reference)
#include <cuda_runtime.h>
#include <cuda_fp16.h>
#include <math.h>
#include <stdint.h>

#define DDIM 256
#define NQMAX 40000

// ---------------- scratch (device globals; zero-initialized, no allocation) --
__device__ __align__(16) float g_oa  [NQMAX * 144];    // offsets+logits
__device__ __align__(16) float g_y   [NQMAX * DDIM];   // ln1 fp32 (residual for ln2)

// fp16 activation streams
__device__ __align__(16) __half g_q16[NQMAX * DDIM];   // query
__device__ __align__(16) __half g_a16[NQMAX * DDIM];   // value input
__device__ __align__(16) __half g_v16[NQMAX * DDIM];   // value projection
__device__ __align__(16) __half g_m16[NQMAX * DDIM];   // msda out
__device__ __align__(16) __half g_y16[NQMAX * DDIM];   // ln1 out
__device__ __align__(16) __half g_h16[NQMAX * DDIM];   // gelu hidden

// transposed fp16 weights: [N][K=256]   (oa padded to 256 rows, zeros)
__device__ __align__(16) __half g_bv[DDIM * DDIM];
__device__ __align__(16) __half g_bo[DDIM * DDIM];
__device__ __align__(16) __half g_b1[DDIM * DDIM];
__device__ __align__(16) __half g_b2[DDIM * DDIM];
__device__ __align__(16) __half g_boaw[DDIM * DDIM];
__device__ __align__(16) float g_boa[144];

// ---------------- helpers ------------------------------------------------------
__device__ __forceinline__ uint32_t smem_u32(const void* p) {
    uint32_t a;
    asm("{ .reg .u64 t; cvta.to.shared.u64 t, %1; cvt.u32.u64 %0, t; }" : "=r"(a) : "l"(p));
    return a;
}

__device__ __forceinline__ uint32_t pack_h2(__half x, __half y) {
    __half2 t(x, y);
    return *reinterpret_cast<uint32_t*>(&t);
}

__device__ __forceinline__ float gelu_exact(float x) {
    return 0.5f * x * (1.0f + erff(x * 0.70710678118654752f));
}

#define LDSM4(r, addr) \
    asm volatile("ldmatrix.sync.aligned.m8n8.x4.shared.b16 {%0,%1,%2,%3}, [%4];" \
        : "=r"((r)[0]), "=r"((r)[1]), "=r"((r)[2]), "=r"((r)[3]) : "r"(addr))

#define CP_ASYNC16(dst, src) \
    asm volatile("cp.async.ca.shared.global [%0], [%1], 16;" :: "r"(dst), "l"(src))
#define CP_ASYNC16Z(dst, src, sz) \
    asm volatile("cp.async.ca.shared.global [%0], [%1], 16, %2;" \
                 :: "r"(dst), "l"(src), "r"(sz))
#define CP_COMMIT() asm volatile("cp.async.commit_group;" ::: "memory")
#define CP_WAIT(n)  asm volatile("cp.async.wait_group %0;" :: "n"(n) : "memory")

__device__ __forceinline__ void mma_f16(float* d, const uint32_t* a,
                                        uint32_t b0, uint32_t b1) {
    asm volatile(
        "mma.sync.aligned.m16n8k16.row.col.f32.f16.f16.f32 "
        "{%0,%1,%2,%3}, {%4,%5,%6,%7}, {%8,%9}, {%0,%1,%2,%3};"
        : "+f"(d[0]), "+f"(d[1]), "+f"(d[2]), "+f"(d[3])
        : "r"(a[0]), "r"(a[1]), "r"(a[2]), "r"(a[3]), "r"(b0), "r"(b1));
}

// ---------------- HMMA GEMM v9 (unchanged): 256 thr, 128x128, 4-stage ----------
// MODE 0: fp32 Cf.  MODE 1: gelu -> fp16 Ch.  MODE 2: fp16 Ch (no gelu).
template<int MODE, int FULLN>
__global__ __launch_bounds__(256, 2)
void gemm_mma(const __half* __restrict__ A,
              const __half* __restrict__ B,
              const float* __restrict__ bias,
              float* __restrict__ Cf, __half* __restrict__ Ch,
              int M, int N) {
    extern __shared__ __align__(128) char smem[];
    const uint32_t sb = smem_u32(smem);
    const int tid = threadIdx.x;
    const int wid = tid >> 5;
    const int lane = tid & 31;
    const int m0 = blockIdx.y * 128;
    const int n0 = blockIdx.x * 128;
    const int wr = wid & 3;
    const int wc = wid >> 2;

    constexpr int RB = 48;
    constexpr int STG = 128 * RB;
    constexpr int SSTR = 2 * STG;

    int nbLim = 4;
    if (!FULLN) {
        const int rem = N - n0 - wc * 64;
        nbLim = rem >= 64 ? 4 : (rem <= 0 ? 0 : (rem + 15) >> 4);
    }

    float acc[2][8][4];
#pragma unroll
    for (int i = 0; i < 2; ++i)
#pragma unroll
        for (int j = 0; j < 8; ++j)
#pragma unroll
            for (int k = 0; k < 4; ++k) acc[i][j][k] = 0.f;

    const int row = tid >> 1;
    const int half = tid & 1;
    const uint32_t dstOff = row * RB + half * 16;
    const int arow = min(m0 + row, M - 1);
    const uint32_t aValid = (m0 + row < M) ? 16u : 0u;
    const __half* aSrc = A + (size_t)arow * DDIM + half * 8;
    const __half* bSrc = B + (size_t)(n0 + row) * DDIM + half * 8;

#define ISSUE(c) do { \
    const uint32_t base = sb + ((c) & 3) * SSTR + dstOff; \
    CP_ASYNC16Z(base,       aSrc + (c) * 16, aValid); \
    CP_ASYNC16(base + STG,  bSrc + (c) * 16); \
    CP_COMMIT(); } while (0)

    ISSUE(0);
    ISSUE(1);
    ISSUE(2);

    const uint32_t lmA = (wr * 32 + (lane & 15)) * RB + (lane >> 4) * 16;
    const uint32_t lmB = (wc * 64 + (lane & 15)) * RB + (lane >> 4) * 16;

    for (int c = 0; c < 16; ++c) {
        const uint32_t stg = sb + (c & 3) * SSTR;
        if (c <= 13)      CP_WAIT(2);
        else if (c == 14) CP_WAIT(1);
        else              CP_WAIT(0);
        __syncthreads();
        if (c + 3 < 16) ISSUE(c + 3);

        uint32_t ah[2][4];
#pragma unroll
        for (int mr = 0; mr < 2; ++mr)
            LDSM4(ah[mr], stg + lmA + mr * 16 * RB);

#pragma unroll
        for (int nb = 0; nb < 4; ++nb) {
            if (!FULLN && nb >= nbLim) break;
            uint32_t bh[4];
            LDSM4(bh, stg + STG + lmB + nb * 16 * RB);
#pragma unroll
            for (int mr = 0; mr < 2; ++mr) {
                mma_f16(acc[mr][nb * 2 + 0], ah[mr], bh[0], bh[2]);
                mma_f16(acc[mr][nb * 2 + 1], ah[mr], bh[1], bh[3]);
            }
        }
    }

#pragma unroll
    for (int mr = 0; mr < 2; ++mr) {
        const int r0 = m0 + wr * 32 + mr * 16 + (lane >> 2);
#pragma unroll
        for (int f = 0; f < 8; ++f) {
            const int col = n0 + wc * 64 + f * 8 + (lane & 3) * 2;
            if (col >= N) continue;
            const float b0 = bias[col], b1 = bias[col + 1];
#pragma unroll
            for (int h = 0; h < 2; ++h) {
                const int r = r0 + h * 8;
                if (r >= M) continue;
                float x0 = acc[mr][f][h * 2 + 0] + b0;
                float x1 = acc[mr][f][h * 2 + 1] + b1;
                if (MODE == 1) { x0 = gelu_exact(x0); x1 = gelu_exact(x1); }
                if (MODE >= 1) {
                    *reinterpret_cast<uint32_t*>(Ch + (size_t)r * DDIM + col) =
                        pack_h2(__float2half(x0), __float2half(x1));
                } else {
                    *reinterpret_cast<float2*>(Cf + (size_t)r * N + col) = make_float2(x0, x1);
                }
            }
        }
    }
#undef ISSUE
}

// ---------------- fused GEMM + bias + residual + LayerNorm ---------------------
// 512 threads, CTA tile 128x256 (full row). 16 warps (wr=wid&3, wc=wid>>2),
// warp tile 32x64. Mainloop = v9 pattern. Epilogue: fp32 LN (bit-compatible
// with ln_kernel). WRITE16=1: also emit fp16 copy of normalized output.
template<int WRITE16>
__global__ __launch_bounds__(512, 1)
void gemm_ln(const __half* __restrict__ A, const __half* __restrict__ B,
             const float* __restrict__ bias, const float* __restrict__ res,
             const float* __restrict__ lng, const float* __restrict__ lnb,
             float* __restrict__ out32, __half* __restrict__ out16, int M) {
    extern __shared__ __align__(128) char smem[];
    const uint32_t sb = smem_u32(smem);
    const int tid = threadIdx.x;
    const int wid = tid >> 5;
    const int lane = tid & 31;
    const int m0 = blockIdx.x * 128;
    const int wr = wid & 3;
    const int wc = wid >> 2;          // 0..3: 64-col slab

    constexpr int RB = 48;
    constexpr int STG_A = 128 * RB;        // 6144
    constexpr int STG_B = 256 * RB;        // 12288
    constexpr int SSTR  = STG_A + STG_B;   // 18432; 4 stages = 73728

    float acc[2][8][4];
#pragma unroll
    for (int i = 0; i < 2; ++i)
#pragma unroll
        for (int j = 0; j < 8; ++j)
#pragma unroll
            for (int k = 0; k < 4; ++k) acc[i][j][k] = 0.f;

    const int row = tid >> 1;          // A: 0..127 (tid<256); B: 0..255
    const int half = tid & 1;
    const uint32_t dOffA = row * RB + half * 16;
    const uint32_t dOffB = row * RB + half * 16;
    const int arow = min(m0 + (row & 127), M - 1);
    const uint32_t aValid = (tid < 256 && m0 + row < M) ? 16u : 0u;
    const __half* aSrc = A + (size_t)arow * DDIM + half * 8;
    const __half* bSrc = B + (size_t)row * DDIM + half * 8;

#define ISSUE(c) do { \
    const uint32_t base = sb + ((c) & 3) * SSTR; \
    if (tid < 256) CP_ASYNC16Z(base + dOffA, aSrc + (c) * 16, aValid); \
    CP_ASYNC16(base + STG_A + dOffB, bSrc + (c) * 16); \
    CP_COMMIT(); } while (0)

    ISSUE(0);
    ISSUE(1);
    ISSUE(2);

    const uint32_t lmA = (wr * 32 + (lane & 15)) * RB + (lane >> 4) * 16;
    const uint32_t lmB = (wc * 64 + (lane & 15)) * RB + (lane >> 4) * 16;

    for (int c = 0; c < 16; ++c) {
        const uint32_t stg = sb + (c & 3) * SSTR;
        if (c <= 13)      CP_WAIT(2);
        else if (c == 14) CP_WAIT(1);
        else              CP_WAIT(0);
        __syncthreads();
        if (c + 3 < 16) ISSUE(c + 3);

        uint32_t ah[2][4];
#pragma unroll
        for (int mr = 0; mr < 2; ++mr)
            LDSM4(ah[mr], stg + lmA + mr * 16 * RB);

#pragma unroll
        for (int nb = 0; nb < 4; ++nb) {
            uint32_t bh[4];
            LDSM4(bh, stg + STG_A + lmB + nb * 16 * RB);
#pragma unroll
            for (int mr = 0; mr < 2; ++mr) {
                mma_f16(acc[mr][nb * 2 + 0], ah[mr], bh[0], bh[2]);
                mma_f16(acc[mr][nb * 2 + 1], ah[mr], bh[1], bh[3]);
            }
        }
    }

    // ---- epilogue phase 1: bias+residual, per-row partial sums ----
    __syncthreads();                       // all LDSM reads of smem done
    float2* rowPart = reinterpret_cast<float2*>(smem);   // [128][4]

    float2 bs[8];
#pragma unroll
    for (int f = 0; f < 8; ++f)
        bs[f] = *reinterpret_cast<const float2*>(bias + wc * 64 + f * 8 + (lane & 3) * 2);

#pragma unroll
    for (int mr = 0; mr < 2; ++mr) {
#pragma unroll
        for (int h = 0; h < 2; ++h) {
            const int rl = wr * 32 + mr * 16 + h * 8 + (lane >> 2);
            const int r = m0 + rl;
            float s = 0.f, s2 = 0.f;
            if (r < M) {
#pragma unroll
                for (int f = 0; f < 8; ++f) {
                    const int col = wc * 64 + f * 8 + (lane & 3) * 2;
                    const float2 rr = *reinterpret_cast<const float2*>(
                        res + (size_t)r * DDIM + col);
                    const float v0 = acc[mr][f][h * 2 + 0] + bs[f].x + rr.x;
                    const float v1 = acc[mr][f][h * 2 + 1] + bs[f].y + rr.y;
                    s += v0 + v1;
                    s2 += v0 * v0 + v1 * v1;
                }
            }
#pragma unroll
            for (int o = 1; o <= 2; o <<= 1) {
                s  += __shfl_xor_sync(0xffffffffu, s, o);
                s2 += __shfl_xor_sync(0xffffffffu, s2, o);
            }
            if ((lane & 3) == 0) rowPart[rl * 4 + wc] = make_float2(s, s2);
        }
    }
    __syncthreads();

    // ---- epilogue phase 2: normalize + write ----
#pragma unroll
    for (int mr = 0; mr < 2; ++mr) {
#pragma unroll
        for (int h = 0; h < 2; ++h) {
            const int rl = wr * 32 + mr * 16 + h * 8 + (lane >> 2);
            const int r = m0 + rl;
            if (r >= M) continue;
            const float2 p0 = rowPart[rl * 4 + 0];
            const float2 p1 = rowPart[rl * 4 + 1];
            const float2 p2 = rowPart[rl * 4 + 2];
            const float2 p3 = rowPart[rl * 4 + 3];
            const float S  = p0.x + p1.x + p2.x + p3.x;
            const float S2 = p0.y + p1.y + p2.y + p3.y;
            const float mean = S * (1.f / 256.f);
            const float var  = S2 * (1.f / 256.f) - mean * mean;
            const float rstd = rsqrtf(var + 1e-5f);
#pragma unroll
            for (int f = 0; f < 8; ++f) {
                const int col = wc * 64 + f * 8 + (lane & 3) * 2;
                const float2 rr = *reinterpret_cast<const float2*>(
                    res + (size_t)r * DDIM + col);
                const float v0 = acc[mr][f][h * 2 + 0] + bs[f].x + rr.x;
                const float v1 = acc[mr][f][h * 2 + 1] + bs[f].y + rr.y;
                const float2 gg = *reinterpret_cast<const float2*>(lng + col);
                const float2 bb = *reinterpret_cast<const float2*>(lnb + col);
                const float o0 = (v0 - mean) * rstd * gg.x + bb.x;
                const float o1 = (v1 - mean) * rstd * gg.y + bb.y;
                *reinterpret_cast<float2*>(out32 + (size_t)r * DDIM + col) =
                    make_float2(o0, o1);
                if (WRITE16)
                    *reinterpret_cast<uint32_t*>(out16 + (size_t)r * DDIM + col) =
                        pack_h2(__float2half(o0), __float2half(o1));
            }
        }
    }
#undef ISSUE
}

// ---------------- fp32 -> fp16 activation convert ------------------------------
__global__ __launch_bounds__(256)
void split_act(const float* __restrict__ x, __half* __restrict__ h, int n4) {
    const int i = blockIdx.x * 256 + threadIdx.x;
    if (i >= n4) return;
    const float4 v = __ldg(reinterpret_cast<const float4*>(x) + i);
    uint2 hv = make_uint2(pack_h2(__float2half(v.x), __float2half(v.y)),
                          pack_h2(__float2half(v.z), __float2half(v.w)));
    *reinterpret_cast<uint2*>(h + (size_t)i * 4) = hv;
}

// ---------------- weight transpose + fp16 convert ------------------------------
__global__ __launch_bounds__(256)
void convert_weights(const float* __restrict__ Wv, const float* __restrict__ Wo,
                     const float* __restrict__ W1, const float* __restrict__ W2,
                     const float* __restrict__ Woff, const float* __restrict__ Wattn,
                     const float* __restrict__ boff, const float* __restrict__ battn) {
    const int b = blockIdx.x;
    const int k = threadIdx.x;
    if (b == 1168) {
        if (k < 96) g_boa[k] = boff[k];
        else if (k < 144) g_boa[k] = battn[k - 96];
        return;
    }
    const float* W; __half* oh; int n, nout, N;
    if (b < 256)       { W = Wv; oh = g_bv; n = b;        nout = n; N = 256; }
    else if (b < 512)  { W = Wo; oh = g_bo; n = b - 256;  nout = n; N = 256; }
    else if (b < 768)  { W = W1; oh = g_b1; n = b - 512;  nout = n; N = 256; }
    else if (b < 1024) { W = W2; oh = g_b2; n = b - 768;  nout = n; N = 256; }
    else {
        nout = b - 1024;
        oh = g_boaw;
        if (nout < 96) { W = Woff;  n = nout;      N = 96; }
        else           { W = Wattn; n = nout - 96; N = 48; }
    }
    oh[(size_t)nout * DDIM + k] = __float2half(W[(size_t)k * N + n]);
}

// ---------------- MSDA sampling v4 (unchanged from R15) ------------------------
__global__ __launch_bounds__(256)
void msda_sample_kernel(const float* __restrict__ oa, const __half* __restrict__ v,
                        const float* __restrict__ ref, const int* __restrict__ ss,
                        __half* __restrict__ out) {
    const int q = blockIdx.x;
    const int h = threadIdx.x >> 5;
    const int lane = threadIdx.x & 31;
    const int cg = lane & 3;
    const int corner = (lane >> 2) & 3;
    const int psub = lane >> 4;

    const int H = ss[0];
    const int W = ss[1];

    const float bx = __ldg(ref + q * 2 + 0) * (float)W - 0.5f;
    const float by = __ldg(ref + q * 2 + 1) * (float)H - 0.5f;

    const float* qa = oa + (size_t)q * 144;

    const int p_m = lane >> 2;
    const int c_m = lane & 3;
    const bool metaValid = (p_m < 6);

    float lg_own = metaValid ? __ldg(qa + 96 + h * 6 + p_m) : -1e30f;
    float mx = lg_own;
#pragma unroll
    for (int o = 4; o <= 16; o <<= 1)
        mx = fmaxf(mx, __shfl_xor_sync(0xffffffffu, mx, o));
    float e = metaValid ? __expf(lg_own - mx) : 0.f;
    float sum = e;
#pragma unroll
    for (int o = 4; o <= 16; o <<= 1)
        sum += __shfl_xor_sync(0xffffffffu, sum, o);
    const float a_own = e / sum;

    const int pp = metaValid ? p_m : 0;
    const float ox = __ldg(qa + h * 12 + pp * 2 + 0);
    const float oy = __ldg(qa + h * 12 + pp * 2 + 1);
    const float lx = bx + ox;
    const float ly = by + oy;
    const float x0f = floorf(lx);
    const float y0f = floorf(ly);
    const float fx = lx - x0f;
    const float fy = ly - y0f;
    const int dxm = c_m & 1;
    const int dym = c_m >> 1;
    const int xi = (int)x0f + dxm;
    const int yi = (int)y0f + dym;
    const float wx = dxm ? fx : 1.f - fx;
    const float wy = dym ? fy : 1.f - fy;
    const bool valid = metaValid & (xi >= 0) & (xi < W) & (yi >= 0) & (yi < H);
    const float wv = valid ? a_own * wx * wy : 0.f;
    const uint32_t xc = (uint32_t)min(max(xi, 0), W - 1);
    const uint32_t yc = (uint32_t)min(max(yi, 0), H - 1);
    const uint32_t off_own = (yc * (uint32_t)W + xc) * 32u;

    const uint4* vh = reinterpret_cast<const uint4*>(v) + (h * 4 + cg);
    float acc[8];
#pragma unroll
    for (int j = 0; j < 8; ++j) acc[j] = 0.f;

#pragma unroll
    for (int i = 0; i < 3; ++i) {
        const int p = 2 * i + psub;
        const int src = p * 4 + corner;
        const uint32_t off = __shfl_sync(0xffffffffu, off_own, src);
        const float w = __shfl_sync(0xffffffffu, wv, src);
        const uint4 raw = __ldg(vh + off);
        const __half2* hp = reinterpret_cast<const __half2*>(&raw);
#pragma unroll
        for (int j = 0; j < 4; ++j) {
            const float2 f = __half22float2(hp[j]);
            acc[2 * j + 0] += w * f.x;
            acc[2 * j + 1] += w * f.y;
        }
    }

#pragma unroll
    for (int o = 4; o <= 16; o <<= 1) {
#pragma unroll
        for (int j = 0; j < 8; ++j)
            acc[j] += __shfl_xor_sync(0xffffffffu, acc[j], o);
    }
    if (lane < 4) {
        uint4 hv;
        hv.x = pack_h2(__float2half(acc[0]), __float2half(acc[1]));
        hv.y = pack_h2(__float2half(acc[2]), __float2half(acc[3]));
        hv.z = pack_h2(__float2half(acc[4]), __float2half(acc[5]));
        hv.w = pack_h2(__float2half(acc[6]), __float2half(acc[7]));
        *reinterpret_cast<uint4*>(out + (size_t)q * DDIM + h * 32 + cg * 8) = hv;
    }
}

// ---------------- launch --------------------------------------------------------
extern "C" void kernel_launch(void* const* d_in, const int* in_sizes, int n_in,
                              void* d_out, int out_size) {
    const float* query  = (const float*)d_in[0];
    const float* value  = (const float*)d_in[1];
    const float* refp   = (const float*)d_in[2];
    const int*   ss     = (const int*)d_in[3];
    const float* W_off  = (const float*)d_in[5];
    const float* b_off  = (const float*)d_in[6];
    const float* W_attn = (const float*)d_in[7];
    const float* b_attn = (const float*)d_in[8];
    const float* W_val  = (const float*)d_in[9];
    const float* b_val  = (const float*)d_in[10];
    const float* W_out  = (const float*)d_in[11];
    const float* b_out  = (const float*)d_in[12];
    const float* ln1_g  = (const float*)d_in[13];
    const float* ln1_b  = (const float*)d_in[14];
    const float* W1     = (const float*)d_in[15];
    const float* b1     = (const float*)d_in[16];
    const float* W2     = (const float*)d_in[17];
    const float* b2     = (const float*)d_in[18];
    const float* ln2_g  = (const float*)d_in[19];
    const float* ln2_b  = (const float*)d_in[20];
    float* out = (float*)d_out;

    const int M  = in_sizes[0] / DDIM;
    const int Mv = in_sizes[1] / DDIM;

    float *poa, *py, *pboa;
    __half *q16, *a16, *v16, *m16, *y16, *h16;
    __half *bv, *bo, *b1w, *b2w, *boaw;
    cudaGetSymbolAddress((void**)&poa,   g_oa);
    cudaGetSymbolAddress((void**)&py,    g_y);
    cudaGetSymbolAddress((void**)&pboa,  g_boa);
    cudaGetSymbolAddress((void**)&q16,   g_q16);
    cudaGetSymbolAddress((void**)&a16,   g_a16);
    cudaGetSymbolAddress((void**)&v16,   g_v16);
    cudaGetSymbolAddress((void**)&m16,   g_m16);
    cudaGetSymbolAddress((void**)&y16,   g_y16);
    cudaGetSymbolAddress((void**)&h16,   g_h16);
    cudaGetSymbolAddress((void**)&bv,    g_bv);
    cudaGetSymbolAddress((void**)&bo,    g_bo);
    cudaGetSymbolAddress((void**)&b1w,   g_b1);
    cudaGetSymbolAddress((void**)&b2w,   g_b2);
    cudaGetSymbolAddress((void**)&boaw,  g_boaw);

    const int SMEM   = 8 * 128 * 48;                 // 49152 (v9, 4 stages)
    const int SMEMLN = 4 * (128 * 48 + 256 * 48);    // 73728 (fused, 4 stages)
    cudaFuncSetAttribute((gemm_mma<0, 0>), cudaFuncAttributeMaxDynamicSharedMemorySize, SMEM);
    cudaFuncSetAttribute((gemm_mma<1, 1>), cudaFuncAttributeMaxDynamicSharedMemorySize, SMEM);
    cudaFuncSetAttribute((gemm_mma<2, 1>), cudaFuncAttributeMaxDynamicSharedMemorySize, SMEM);
    cudaFuncSetAttribute((gemm_ln<0>), cudaFuncAttributeMaxDynamicSharedMemorySize, SMEMLN);
    cudaFuncSetAttribute((gemm_ln<1>), cudaFuncAttributeMaxDynamicSharedMemorySize, SMEMLN);

    const int gM  = (M + 127) / 128;
    const int gMv = (Mv + 127) / 128;

    // 0) weights -> transposed fp16; activations -> fp16
    convert_weights<<<1169, 256>>>(W_val, W_out, W1, W2, W_off, W_attn, b_off, b_attn);
    split_act<<<(M * 64 + 255) / 256, 256>>>(query, q16, M * 64);
    split_act<<<(Mv * 64 + 255) / 256, 256>>>(value, a16, Mv * 64);
    // 1) value projection -> fp16
    gemm_mma<2, 1><<<dim3(2, gMv), 256, SMEM>>>(a16, bv, b_val, nullptr, v16, Mv, DDIM);
    // 2) fused offsets+attn logits GEMM (N=144)
    gemm_mma<0, 0><<<dim3(2, gM), 256, SMEM>>>(q16, boaw, pboa, poa, nullptr, M, 144);
    // 3) deformable sampling -> fp16
    msda_sample_kernel<<<M, 256>>>(poa, v16, refp, ss, m16);
    // 4) output projection + residual + LN1 (fused; emits fp32 y + fp16 y16)
    gemm_ln<1><<<gM, 512, SMEMLN>>>(m16, bo, b_out, query, ln1_g, ln1_b, py, y16, M);
    // 5) FFN: gelu GEMM, then W2 + residual + LN2 fused -> final out
    gemm_mma<1, 1><<<dim3(2, gM), 256, SMEM>>>(y16, b1w, b1, nullptr, h16, M, DDIM);
    gemm_ln<0><<<gM, 512, SMEMLN>>>(h16, b2w, b2, py, ln2_g, ln2_b, out, nullptr, M);
}